// round 15
// baseline (speedup 1.0000x reference)
#include <cuda_runtime.h>
#include <cuda_fp16.h>
#include <math.h>
#include <stdint.h>

#define N_CTX   4096
#define D_MODEL 2048

// ---------------------------------------------------------------------------
// Scratch (__device__ globals; allocation-free rule)
// ---------------------------------------------------------------------------
__device__ __half g_xb16 [(size_t)N_CTX * D_MODEL];
__device__ __half g_xs16 [(size_t)N_CTX * D_MODEL];
__device__ __half g_xT16 [(size_t)D_MODEL * N_CTX];   // x^T, single fp16
__device__ __half g_wqkb16[(size_t)D_MODEL * D_MODEL];
__device__ __half g_wqks16[(size_t)D_MODEL * D_MODEL];
__device__ __half g_wov16 [(size_t)D_MODEL * D_MODEL];
__device__ __half g_Qb16 [(size_t)N_CTX * D_MODEL];
__device__ __half g_Qs16 [(size_t)N_CTX * D_MODEL];
__device__ float  g_S    [(size_t)N_CTX * N_CTX];
__device__ __half g_P16  [(size_t)N_CTX * N_CTX];
__device__ __half g_A16  [(size_t)N_CTX * D_MODEL];

// ---------------------------------------------------------------------------
// helpers
// ---------------------------------------------------------------------------
__device__ __forceinline__ void mma_f16(float c[4],
                                        uint32_t a0, uint32_t a1, uint32_t a2, uint32_t a3,
                                        uint32_t b0, uint32_t b1) {
    asm volatile(
        "mma.sync.aligned.m16n8k16.row.col.f32.f16.f16.f32 "
        "{%0,%1,%2,%3}, {%4,%5,%6,%7}, {%8,%9}, {%0,%1,%2,%3};"
        : "+f"(c[0]), "+f"(c[1]), "+f"(c[2]), "+f"(c[3])
        : "r"(a0), "r"(a1), "r"(a2), "r"(a3), "r"(b0), "r"(b1));
}

__device__ __forceinline__ void ldm_x4(uint32_t r[4], uint32_t saddr) {
    asm volatile("ldmatrix.sync.aligned.m8n8.x4.shared.b16 {%0,%1,%2,%3}, [%4];"
                 : "=r"(r[0]), "=r"(r[1]), "=r"(r[2]), "=r"(r[3]) : "r"(saddr));
}

__device__ __forceinline__ void cp_async16(void* smem, const void* gmem) {
    uint32_t s = (uint32_t)__cvta_generic_to_shared(smem);
    asm volatile("cp.async.cg.shared.global [%0], [%1], 16;" :: "r"(s), "l"(gmem));
}
__device__ __forceinline__ void cp_commit() {
    asm volatile("cp.async.commit_group;" ::: "memory");
}
template <int Nn>
__device__ __forceinline__ void cp_wait() {
    asm volatile("cp.async.wait_group %0;" :: "n"(Nn) : "memory");
}

// ---------------------------------------------------------------------------
// Elementwise pre-passes
// ---------------------------------------------------------------------------
__global__ __launch_bounds__(256)
void prep_x_kernel(const float* __restrict__ x,
                   __half* __restrict__ xb, __half* __restrict__ xs,
                   __half* __restrict__ xT, int R, int Cc)
{
    __shared__ float t[32][33];
    const int bx = blockIdx.x * 32, by = blockIdx.y * 32;
    const int tx = threadIdx.x, ty = threadIdx.y;
    const int col = bx + tx;
    for (int i = ty; i < 32; i += 8) {
        float v = x[(size_t)(by + i) * Cc + col];
        t[i][tx] = v;
        __half b = __float2half_rn(v);
        size_t off = (size_t)(by + i) * Cc + col;
        xb[off] = b;
        xs[off] = __float2half_rn(v - __half2float(b));
    }
    __syncthreads();
    const int orow = by + tx;
    for (int i = ty; i < 32; i += 8)
        xT[(size_t)(bx + i) * R + orow] = __float2half_rn(t[tx][i]);
}

__global__ __launch_bounds__(256)
void split_f16_kernel(const float* __restrict__ src,
                      __half* __restrict__ big, __half* __restrict__ sml, int n4)
{
    int i = blockIdx.x * 256 + threadIdx.x;
    if (i >= n4) return;
    float4 v = ((const float4*)src)[i];
    __half b0 = __float2half_rn(v.x), b1 = __float2half_rn(v.y);
    __half b2 = __float2half_rn(v.z), b3 = __float2half_rn(v.w);
    ((__half2*)big)[i * 2 + 0] = __halves2half2(b0, b1);
    ((__half2*)big)[i * 2 + 1] = __halves2half2(b2, b3);
    ((__half2*)sml)[i * 2 + 0] = __halves2half2(
        __float2half_rn(v.x - __half2float(b0)), __float2half_rn(v.y - __half2float(b1)));
    ((__half2*)sml)[i * 2 + 1] = __halves2half2(
        __float2half_rn(v.z - __half2float(b2)), __float2half_rn(v.w - __half2float(b3)));
}

__global__ __launch_bounds__(256)
void round_f16_kernel(const float* __restrict__ src, __half* __restrict__ dst, int n4)
{
    int i = blockIdx.x * 256 + threadIdx.x;
    if (i >= n4) return;
    float4 v = ((const float4*)src)[i];
    ((__half2*)dst)[i * 2 + 0] = __halves2half2(__float2half_rn(v.x), __float2half_rn(v.y));
    ((__half2*)dst)[i * 2 + 1] = __halves2half2(__float2half_rn(v.z), __float2half_rn(v.w));
}

// ---------------------------------------------------------------------------
// fp16 split GEMM: C[M,N] = A[M,K] @ B^T, A:[M,K], B:[N,K], both K-major fp16.
//   PASSES=3: As*Bb + Ab*Bs + Ab*Bb;  PASSES=1: Ab*Bb only
//   CSKIP: skip blocks above diagonal; CK: k-range limited to m0+128
//   EPI: 0 = fp32 store; 1 = split fp16 store Cb/Cs; 2 = single fp16 Cb
//   NS:  pipeline stages. NS=2: two barriers/k-tile (needs OCC=2 to hide).
//        NS=3: single barrier/k-tile.
// 256 threads, 8 warps (2x4), warp tile 64x32, block 128x128x32, m16n8k16,
// ldmatrix.x4 loads (PK=40 conflict-free), dynamic smem.
// ---------------------------------------------------------------------------
template <int CSKIP, int CK, int PASSES, int EPI, int OCC, int NS>
__global__ __launch_bounds__(256, OCC)
void hgemm(const __half* __restrict__ Ab_, const __half* __restrict__ As_,
           const __half* __restrict__ Bb_, const __half* __restrict__ Bs_,
           float* __restrict__ C, __half* __restrict__ Cb, __half* __restrict__ Cs,
           int M, int N, int K)
{
    constexpr int BM = 128, BN = 128, BK = 32, PK = 40;
    constexpr int TILE_H = BM * PK;              // halves per tile array (5120)
    constexpr int ARR = (PASSES == 3) ? 4 : ((PASSES == 2) ? 3 : 2);

    extern __shared__ __half dsm[];

    const int m0 = blockIdx.y * BM;
    const int n0 = blockIdx.x * BN;
    if (CSKIP && n0 >= m0 + BM) return;

    const int kEnd = CK ? min(K, m0 + BM) : K;
    const int nK   = kEnd / BK;

    const int tid  = threadIdx.x;
    const int warp = tid >> 5;
    const int lane = tid & 31;
    const int wm0  = (warp & 1) * 64;
    const int wn0  = (warp >> 1) * 32;
    const int g    = lane >> 2;
    const int tg   = lane & 3;

    const int lm  = lane >> 3;
    const int lr  = lane & 7;
    const int aRow = (lm & 1) * 8 + lr;
    const int aCol = (lm >> 1) * 8;
    const int bRow = (lm >> 1) * 8 + lr;
    const int bCol = (lm & 1) * 8;

    const uint32_t u0 = (uint32_t)__cvta_generic_to_shared(dsm);
    constexpr uint32_t STAGE_B = (uint32_t)ARR * TILE_H * 2;
    constexpr uint32_t OFF_B   = (uint32_t)TILE_H * 2;
    constexpr uint32_t OFF_AS  = (uint32_t)2 * TILE_H * 2;
    constexpr uint32_t OFF_BS  = (uint32_t)3 * TILE_H * 2;

    float acc[4][4][4];
    #pragma unroll
    for (int i = 0; i < 4; i++)
        #pragma unroll
        for (int j = 0; j < 4; j++)
            #pragma unroll
            for (int r = 0; r < 4; r++) acc[i][j][r] = 0.0f;

    auto loadStage = [&](int s, int k0) {
        __half* st = dsm + (size_t)s * ARR * TILE_H;
        #pragma unroll
        for (int i = 0; i < 2; i++) {
            int idx = tid + i * 256;
            int row = idx >> 2;
            int c8  = (idx & 3) * 8;
            cp_async16(st + row * PK + c8,              Ab_ + (size_t)(m0 + row) * K + k0 + c8);
            cp_async16(st + TILE_H + row * PK + c8,     Bb_ + (size_t)(n0 + row) * K + k0 + c8);
            if constexpr (PASSES >= 2)
                cp_async16(st + 2 * TILE_H + row * PK + c8, As_ + (size_t)(m0 + row) * K + k0 + c8);
            if constexpr (PASSES == 3)
                cp_async16(st + 3 * TILE_H + row * PK + c8, Bs_ + (size_t)(n0 + row) * K + k0 + c8);
        }
    };

    auto compute = [&](int s) {
        const uint32_t ub = u0 + (uint32_t)s * STAGE_B;
        #pragma unroll
        for (int ks = 0; ks < 2; ks++) {
            const int kb = ks * 16;
            uint32_t Ab[4][4], As[4][4];
            uint32_t Bb[4][2], Bs[4][2];

            const uint32_t aoff = (uint32_t)((wm0 + aRow) * PK + kb + aCol) * 2;
            const uint32_t boff = (uint32_t)((wn0 + bRow) * PK + kb + bCol) * 2;

            #pragma unroll
            for (int mt = 0; mt < 4; mt++) {
                ldm_x4(Ab[mt], ub + aoff + (uint32_t)(mt * 16 * PK * 2));
                if constexpr (PASSES >= 2)
                    ldm_x4(As[mt], ub + OFF_AS + aoff + (uint32_t)(mt * 16 * PK * 2));
            }
            #pragma unroll
            for (int j = 0; j < 2; j++) {
                uint32_t t[4];
                ldm_x4(t, ub + OFF_B + boff + (uint32_t)(j * 16 * PK * 2));
                Bb[2 * j][0] = t[0]; Bb[2 * j][1] = t[1];
                Bb[2 * j + 1][0] = t[2]; Bb[2 * j + 1][1] = t[3];
                if constexpr (PASSES == 3) {
                    ldm_x4(t, ub + OFF_BS + boff + (uint32_t)(j * 16 * PK * 2));
                    Bs[2 * j][0] = t[0]; Bs[2 * j][1] = t[1];
                    Bs[2 * j + 1][0] = t[2]; Bs[2 * j + 1][1] = t[3];
                }
            }

            if constexpr (PASSES >= 2) {
                #pragma unroll
                for (int mt = 0; mt < 4; mt++)
                    #pragma unroll
                    for (int nt = 0; nt < 4; nt++)
                        mma_f16(acc[mt][nt], As[mt][0], As[mt][1], As[mt][2], As[mt][3],
                                Bb[nt][0], Bb[nt][1]);
            }
            if constexpr (PASSES == 3) {
                #pragma unroll
                for (int mt = 0; mt < 4; mt++)
                    #pragma unroll
                    for (int nt = 0; nt < 4; nt++)
                        mma_f16(acc[mt][nt], Ab[mt][0], Ab[mt][1], Ab[mt][2], Ab[mt][3],
                                Bs[nt][0], Bs[nt][1]);
            }
            #pragma unroll
            for (int mt = 0; mt < 4; mt++)
                #pragma unroll
                for (int nt = 0; nt < 4; nt++)
                    mma_f16(acc[mt][nt], Ab[mt][0], Ab[mt][1], Ab[mt][2], Ab[mt][3],
                            Bb[nt][0], Bb[nt][1]);
        }
    };

    if constexpr (NS == 2) {
        // 2-stage double buffer, two barriers per k-tile (OCC=2 hides them).
        loadStage(0, 0);
        cp_commit();
        for (int kt = 0; kt < nK; kt++) {
            if (kt + 1 < nK) {
                loadStage((kt + 1) & 1, (kt + 1) * BK);
                cp_commit();
                cp_wait<1>();
            } else {
                cp_wait<0>();
            }
            __syncthreads();
            compute(kt & 1);
            __syncthreads();
        }
    } else {
        // 3-stage, single barrier per k-tile.
        loadStage(0, 0);        cp_commit();
        loadStage(1, BK);       cp_commit();
        for (int kt = 0; kt < nK; kt++) {
            cp_wait<1>();
            __syncthreads();
            compute(kt % 3);
            if (kt + 2 < nK) loadStage((kt + 2) % 3, (kt + 2) * BK);
            cp_commit();
        }
    }

    // ---- epilogue ----
    #pragma unroll
    for (int mt = 0; mt < 4; mt++) {
        #pragma unroll
        for (int nt = 0; nt < 4; nt++) {
            int r = m0 + wm0 + mt * 16 + g;
            int c = n0 + wn0 + nt * 8 + 2 * tg;
            #pragma unroll
            for (int h = 0; h < 2; h++) {
                float v0 = acc[mt][nt][h * 2 + 0];
                float v1 = acc[mt][nt][h * 2 + 1];
                size_t off = (size_t)(r + h * 8) * N + c;
                if constexpr (EPI == 0) {
                    *(float2*)(C + off) = make_float2(v0, v1);
                } else if constexpr (EPI == 1) {
                    __half b0 = __float2half_rn(v0), b1 = __float2half_rn(v1);
                    *(__half2*)(Cb + off) = __halves2half2(b0, b1);
                    *(__half2*)(Cs + off) = __halves2half2(
                        __float2half_rn(v0 - __half2float(b0)),
                        __float2half_rn(v1 - __half2float(b1)));
                } else {
                    *(__half2*)(Cb + off) = __halves2half2(__float2half_rn(v0),
                                                           __float2half_rn(v1));
                }
            }
        }
    }
}

// ---------------------------------------------------------------------------
// Causal row softmax: reads fp32 scores, writes single fp16 P (zero tail).
// ---------------------------------------------------------------------------
__global__ __launch_bounds__(256)
void softmax_kernel(float* __restrict__ S, __half* __restrict__ P, int n)
{
    const int row   = blockIdx.x;
    float* srow     = S + (size_t)row * n;
    const int valid = row + 1;
    const int tid   = threadIdx.x;

    __shared__ float red[256];

    float m = -INFINITY;
    for (int j = tid; j < valid; j += 256) m = fmaxf(m, srow[j]);
    red[tid] = m;
    __syncthreads();
    #pragma unroll
    for (int s = 128; s > 0; s >>= 1) {
        if (tid < s) red[tid] = fmaxf(red[tid], red[tid + s]);
        __syncthreads();
    }
    m = red[0];
    __syncthreads();

    float sum = 0.0f;
    for (int j = tid; j < valid; j += 256) {
        float e = __expf(srow[j] - m);
        srow[j] = e;
        sum += e;
    }
    red[tid] = sum;
    __syncthreads();
    #pragma unroll
    for (int s = 128; s > 0; s >>= 1) {
        if (tid < s) red[tid] += red[tid + s];
        __syncthreads();
    }
    const float inv = 1.0f / red[0];

    for (int j = tid; j < n; j += 256) {
        float p = (j < valid) ? srow[j] * inv : 0.0f;
        P[(size_t)row * n + j] = __float2half_rn(p);
    }
}

// ---------------------------------------------------------------------------
extern "C" void kernel_launch(void* const* d_in, const int* in_sizes, int n_in,
                              void* d_out, int out_size)
{
    const float* x   = (const float*)d_in[0];
    const float* Wqk = (const float*)d_in[1];
    const float* Wov = (const float*)d_in[2];
    float* out       = (float*)d_out;

    __half *xb, *xs, *xT, *wqkb, *wqks, *wov, *Qb, *Qs, *P, *A;
    float *S;
    cudaGetSymbolAddress((void**)&xb,   g_xb16);
    cudaGetSymbolAddress((void**)&xs,   g_xs16);
    cudaGetSymbolAddress((void**)&xT,   g_xT16);
    cudaGetSymbolAddress((void**)&wqkb, g_wqkb16);
    cudaGetSymbolAddress((void**)&wqks, g_wqks16);
    cudaGetSymbolAddress((void**)&wov,  g_wov16);
    cudaGetSymbolAddress((void**)&Qb,   g_Qb16);
    cudaGetSymbolAddress((void**)&Qs,   g_Qs16);
    cudaGetSymbolAddress((void**)&S,    g_S);
    cudaGetSymbolAddress((void**)&P,    g_P16);
    cudaGetSymbolAddress((void**)&A,    g_A16);

    const int nw4 = D_MODEL * D_MODEL / 4;

    // Dynamic smem: NS stages x ARR arrays x 5120 halves x 2B
    const int SM3 = 2 * 4 * 128 * 40 * 2;   // 3-pass, 2-stage: 81920 (x2 CTAs = 160KB)
    const int SM1 = 3 * 2 * 128 * 40 * 2;   // 1-pass, 3-stage: 61440 (x2 CTAs = 120KB)

    static bool attr_done = false;
    if (!attr_done) {
        cudaFuncSetAttribute(hgemm<0, 0, 3, 1, 2, 2>, cudaFuncAttributeMaxDynamicSharedMemorySize, SM3);
        cudaFuncSetAttribute(hgemm<1, 0, 3, 0, 2, 2>, cudaFuncAttributeMaxDynamicSharedMemorySize, SM3);
        cudaFuncSetAttribute(hgemm<0, 1, 1, 2, 2, 3>, cudaFuncAttributeMaxDynamicSharedMemorySize, SM1);
        cudaFuncSetAttribute(hgemm<0, 0, 1, 0, 2, 3>, cudaFuncAttributeMaxDynamicSharedMemorySize, SM1);
        attr_done = true;
    }

    // Pre-passes
    prep_x_kernel<<<dim3(D_MODEL / 32, N_CTX / 32), dim3(32, 8)>>>(x, xb, xs, xT, N_CTX, D_MODEL);
    split_f16_kernel<<<(nw4 + 255) / 256, 256>>>(Wqk, wqkb, wqks, nw4);
    round_f16_kernel<<<(nw4 + 255) / 256, 256>>>(Wov, wov, nw4);

    // 1) Q = x @ Wqk^T  (3-pass, 2-stage, 2 CTAs/SM; split store Qb/Qs)
    hgemm<0, 0, 3, 1, 2, 2><<<dim3(D_MODEL / 128, N_CTX / 128), 256, SM3>>>(
        xb, xs, wqkb, wqks, nullptr, Qb, Qs, N_CTX, D_MODEL, D_MODEL);

    // 2) S = Q @ x^T  (causal blocks only, 3-pass, 2-stage, 2 CTAs/SM)
    hgemm<1, 0, 3, 0, 2, 2><<<dim3(N_CTX / 128, N_CTX / 128), 256, SM3>>>(
        Qb, Qs, xb, xs, S, nullptr, nullptr, N_CTX, N_CTX, D_MODEL);

    // 3) P = causal_softmax(S) -> single fp16
    softmax_kernel<<<N_CTX, 256>>>(S, P, N_CTX);

    // 4) A = P @ (x^T)^T  (1-pass, 3-stage; causal k-limit; fp16 store)
    hgemm<0, 1, 1, 2, 2, 3><<<dim3(D_MODEL / 128, N_CTX / 128), 256, SM1>>>(
        P, nullptr, xT, nullptr, nullptr, A, nullptr, N_CTX, D_MODEL, N_CTX);

    // 5) out = A @ Wov^T  (1-pass, 3-stage; fp32 store)
    hgemm<0, 0, 1, 0, 2, 3><<<dim3(D_MODEL / 128, N_CTX / 128), 256, SM1>>>(
        A, nullptr, wov, nullptr, out, nullptr, nullptr, N_CTX, D_MODEL, D_MODEL);
}